// round 7
// baseline (speedup 1.0000x reference)
#include <cuda_runtime.h>

// CrossCompress: B=16384 rows, D=128.
// item_out   = v*(e.w_vv) + e*(v.w_ev) + bias_v
// entity_out = v*(e.w_ve) + e*(v.w_ee) + bias_e
//
// R7: group-per-row layout. Each warp = 4 groups of 8 lanes; group g owns row
// warp*4+g; lane owns 4 float4s (16 elems) of its row. Row reduction is a
// 3-level butterfly within the 8-lane group: 12 SHFLs/warp for 4 rows
// (vs 80 in the lane-per-float4 layout), chain depth 5 -> 3.

#define B_ROWS 16384
#define D_DIM  128

__global__ __launch_bounds__(128)
void crosscompress_kernel(const float4* __restrict__ v_in,
                          const float4* __restrict__ e_in,
                          const float4* __restrict__ w_vv,
                          const float4* __restrict__ w_ve,
                          const float4* __restrict__ w_ev,
                          const float4* __restrict__ w_ee,
                          const float4* __restrict__ bias_v,
                          const float4* __restrict__ bias_e,
                          float4* __restrict__ out_item,
                          float4* __restrict__ out_ent)
{
    const int gtid = blockIdx.x * blockDim.x + threadIdx.x;
    const int warp = gtid >> 5;
    const int lane = gtid & 31;
    const int g    = lane >> 3;      // group: which of 4 rows
    const int l    = lane & 7;       // id within group

    const int row  = warp * 4 + g;
    const int base = row * 32 + l;   // float4 index; lane covers base + 8k

    // Batch the 8 data loads (MLP=8). Each LDG.128 touches 4x128B lines.
    float4 v4[4], e4[4];
    #pragma unroll
    for (int k = 0; k < 4; k++) {
        v4[k] = v_in[base + 8 * k];
        e4[k] = e_in[base + 8 * k];
    }

    // Accumulate 4 partial dots over this lane's 16 elements.
    // Weights are L1-resident; loaded per-k and released.
    float d_vv = 0.f, d_ev = 0.f, d_ve = 0.f, d_ee = 0.f;
    #pragma unroll
    for (int k = 0; k < 4; k++) {
        const int wi = l + 8 * k;
        const float4 wvv = __ldg(&w_vv[wi]);
        const float4 wev = __ldg(&w_ev[wi]);
        const float4 wve = __ldg(&w_ve[wi]);
        const float4 wee = __ldg(&w_ee[wi]);
        d_vv += e4[k].x*wvv.x + e4[k].y*wvv.y + e4[k].z*wvv.z + e4[k].w*wvv.w;
        d_ev += v4[k].x*wev.x + v4[k].y*wev.y + v4[k].z*wev.z + v4[k].w*wev.w;
        d_ve += e4[k].x*wve.x + e4[k].y*wve.y + e4[k].z*wve.z + e4[k].w*wve.w;
        d_ee += v4[k].x*wee.x + v4[k].y*wee.y + v4[k].z*wee.z + v4[k].w*wee.w;
    }

    // 3-level butterfly within the 8-lane group (12 SHFL total, 4 chains)
    #pragma unroll
    for (int off = 1; off <= 4; off <<= 1) {
        d_vv += __shfl_xor_sync(0xFFFFFFFFu, d_vv, off);
        d_ev += __shfl_xor_sync(0xFFFFFFFFu, d_ev, off);
        d_ve += __shfl_xor_sync(0xFFFFFFFFu, d_ve, off);
        d_ee += __shfl_xor_sync(0xFFFFFFFFu, d_ee, off);
    }

    // Combine + store: every lane in the group has the full row sums.
    #pragma unroll
    for (int k = 0; k < 4; k++) {
        const int wi = l + 8 * k;
        const float4 bv = __ldg(&bias_v[wi]);
        const float4 be = __ldg(&bias_e[wi]);

        float4 oi, oe;
        oi.x = v4[k].x*d_vv + e4[k].x*d_ev + bv.x;
        oi.y = v4[k].y*d_vv + e4[k].y*d_ev + bv.y;
        oi.z = v4[k].z*d_vv + e4[k].z*d_ev + bv.z;
        oi.w = v4[k].w*d_vv + e4[k].w*d_ev + bv.w;
        oe.x = v4[k].x*d_ve + e4[k].x*d_ee + be.x;
        oe.y = v4[k].y*d_ve + e4[k].y*d_ee + be.y;
        oe.z = v4[k].z*d_ve + e4[k].z*d_ee + be.z;
        oe.w = v4[k].w*d_ve + e4[k].w*d_ee + be.w;

        out_item[base + 8 * k] = oi;
        out_ent [base + 8 * k] = oe;
    }
}

extern "C" void kernel_launch(void* const* d_in, const int* in_sizes, int n_in,
                              void* d_out, int out_size)
{
    const float4* v_in   = (const float4*)d_in[0];
    const float4* e_in   = (const float4*)d_in[1];
    const float4* w_vv   = (const float4*)d_in[2];
    const float4* w_ve   = (const float4*)d_in[3];
    const float4* w_ev   = (const float4*)d_in[4];
    const float4* w_ee   = (const float4*)d_in[5];
    const float4* bias_v = (const float4*)d_in[6];
    const float4* bias_e = (const float4*)d_in[7];

    float* out = (float*)d_out;
    float4* out_item = (float4*)out;
    float4* out_ent  = (float4*)(out + B_ROWS * D_DIM);

    // 4 warps/block, 4 rows/warp -> 16 rows/block -> 1024 blocks
    const int threads = 128;
    const int blocks  = B_ROWS / 16;   // 1024

    crosscompress_kernel<<<blocks, threads>>>(v_in, e_in, w_vv, w_ve, w_ev, w_ee,
                                              bias_v, bias_e, out_item, out_ent);
}

// round 9
// speedup vs baseline: 1.0295x; 1.0295x over previous
#include <cuda_runtime.h>

// CrossCompress: B=16384 rows, D=128.
// item_out   = v*(e.w_vv) + e*(v.w_ev) + bias_v
// entity_out = v*(e.w_ve) + e*(v.w_ee) + bias_e
//
// R9: R3 geometry (best so far: lane-per-float4, 4 rows/warp, 8 batched
// LDG.128, 128-thr blocks, grid 1024) + streaming stores (__stcs, outputs
// never re-read) + weights/biases hoisted into one batched L1 load group.

#define B_ROWS 16384
#define D_DIM  128
#define RPW    4

__global__ __launch_bounds__(128)
void crosscompress_kernel(const float4* __restrict__ v_in,
                          const float4* __restrict__ e_in,
                          const float4* __restrict__ w_vv,
                          const float4* __restrict__ w_ve,
                          const float4* __restrict__ w_ev,
                          const float4* __restrict__ w_ee,
                          const float4* __restrict__ bias_v,
                          const float4* __restrict__ bias_e,
                          float4* __restrict__ out_item,
                          float4* __restrict__ out_ent)
{
    const int gtid = blockIdx.x * blockDim.x + threadIdx.x;
    const int warp = gtid >> 5;
    const int lane = gtid & 31;
    const int idx0 = (warp * RPW) * 32 + lane;

    // Batch all row loads first: 8 independent LDG.128 (MLP=8)
    float4 v4[RPW], e4[RPW];
    #pragma unroll
    for (int r = 0; r < RPW; r++) {
        v4[r] = v_in[idx0 + r * 32];
        e4[r] = e_in[idx0 + r * 32];
    }

    // Weights + biases: one batched group of 6 L1-resident LDG.128
    const float4 wvv = __ldg(&w_vv[lane]);
    const float4 wev = __ldg(&w_ev[lane]);
    const float4 wve = __ldg(&w_ve[lane]);
    const float4 wee = __ldg(&w_ee[lane]);
    const float4 bv  = __ldg(&bias_v[lane]);
    const float4 be  = __ldg(&bias_e[lane]);

    // 16 independent per-lane partial dots
    float d_vv[RPW], d_ev[RPW], d_ve[RPW], d_ee[RPW];
    #pragma unroll
    for (int r = 0; r < RPW; r++) {
        d_vv[r] = e4[r].x*wvv.x + e4[r].y*wvv.y + e4[r].z*wvv.z + e4[r].w*wvv.w;
        d_ev[r] = v4[r].x*wev.x + v4[r].y*wev.y + v4[r].z*wev.z + v4[r].w*wev.w;
        d_ve[r] = e4[r].x*wve.x + e4[r].y*wve.y + e4[r].z*wve.z + e4[r].w*wve.w;
        d_ee[r] = v4[r].x*wee.x + v4[r].y*wee.y + v4[r].z*wee.z + v4[r].w*wee.w;
    }

    // Butterfly-reduce all 16 values; 16 parallel chains per level
    #pragma unroll
    for (int off = 16; off > 0; off >>= 1) {
        #pragma unroll
        for (int r = 0; r < RPW; r++) {
            d_vv[r] += __shfl_xor_sync(0xFFFFFFFFu, d_vv[r], off);
            d_ev[r] += __shfl_xor_sync(0xFFFFFFFFu, d_ev[r], off);
            d_ve[r] += __shfl_xor_sync(0xFFFFFFFFu, d_ve[r], off);
            d_ee[r] += __shfl_xor_sync(0xFFFFFFFFu, d_ee[r], off);
        }
    }

    #pragma unroll
    for (int r = 0; r < RPW; r++) {
        const int idx = idx0 + r * 32;
        float4 oi, oe;
        oi.x = v4[r].x*d_vv[r] + e4[r].x*d_ev[r] + bv.x;
        oi.y = v4[r].y*d_vv[r] + e4[r].y*d_ev[r] + bv.y;
        oi.z = v4[r].z*d_vv[r] + e4[r].z*d_ev[r] + bv.z;
        oi.w = v4[r].w*d_vv[r] + e4[r].w*d_ev[r] + bv.w;
        oe.x = v4[r].x*d_ve[r] + e4[r].x*d_ee[r] + be.x;
        oe.y = v4[r].y*d_ve[r] + e4[r].y*d_ee[r] + be.y;
        oe.z = v4[r].z*d_ve[r] + e4[r].z*d_ee[r] + be.z;
        oe.w = v4[r].w*d_ve[r] + e4[r].w*d_ee[r] + be.w;

        __stcs(&out_item[idx], oi);
        __stcs(&out_ent[idx],  oe);
    }
}

extern "C" void kernel_launch(void* const* d_in, const int* in_sizes, int n_in,
                              void* d_out, int out_size)
{
    const float4* v_in   = (const float4*)d_in[0];
    const float4* e_in   = (const float4*)d_in[1];
    const float4* w_vv   = (const float4*)d_in[2];
    const float4* w_ve   = (const float4*)d_in[3];
    const float4* w_ev   = (const float4*)d_in[4];
    const float4* w_ee   = (const float4*)d_in[5];
    const float4* bias_v = (const float4*)d_in[6];
    const float4* bias_e = (const float4*)d_in[7];

    float* out = (float*)d_out;
    float4* out_item = (float4*)out;
    float4* out_ent  = (float4*)(out + B_ROWS * D_DIM);

    // 4 warps/block, 4 rows/warp -> 16 rows/block -> 1024 blocks
    const int threads = 128;
    const int blocks  = B_ROWS / (4 * RPW);   // 1024

    crosscompress_kernel<<<blocks, threads>>>(v_in, e_in, w_vv, w_ve, w_ev, w_ee,
                                              bias_v, bias_e, out_item, out_ent);
}